// round 2
// baseline (speedup 1.0000x reference)
#include <cuda_runtime.h>
#include <cstdint>

#define M_MOL 64
#define N_ATM 512
#define RC2 49.0f      // (cutoff + shell)^2 = 7^2
#define I_TILE 8
#define NTHREADS 128   // 128 threads x 4 j each = 512 j

__global__ __launch_bounds__(NTHREADS) void nbl_kernel(
    const float* __restrict__ pos,   // [64, 512, 3]
    float* __restrict__ out)         // [64, 512, 512, 3]
{
    // SoA smem: conflict-free LDS.128 of 4 consecutive j
    __shared__ float sx[N_ATM], sy[N_ATM], sz[N_ATM];

    const int m = blockIdx.y;
    const float* pm = pos + (size_t)m * N_ATM * 3;

    // cooperative AoS -> SoA load (one-time, 1536 elements)
    for (int t = threadIdx.x; t < N_ATM * 3; t += NTHREADS) {
        const float v = pm[t];
        const int a = t / 3;
        const int c = t - 3 * a;
        if (c == 0)      sx[a] = v;
        else if (c == 1) sy[a] = v;
        else             sz[a] = v;
    }
    __syncthreads();

    const int i0 = blockIdx.x * I_TILE;
    const int j0 = threadIdx.x * 4;

    // load this thread's 4 j positions once; reuse across all I_TILE i's
    const float4 px = *reinterpret_cast<const float4*>(&sx[j0]);
    const float4 py = *reinterpret_cast<const float4*>(&sy[j0]);
    const float4 pz = *reinterpret_cast<const float4*>(&sz[j0]);

    #pragma unroll
    for (int ii = 0; ii < I_TILE; ii++) {
        const int i = i0 + ii;
        // broadcast reads (all lanes same address)
        const float xi = sx[i];
        const float yi = sy[i];
        const float zi = sz[i];

        float dx[4], dy[4], dz[4];
        dx[0] = px.x - xi; dy[0] = py.x - yi; dz[0] = pz.x - zi;
        dx[1] = px.y - xi; dy[1] = py.y - yi; dz[1] = pz.y - zi;
        dx[2] = px.z - xi; dy[2] = py.z - yi; dz[2] = pz.z - zi;
        dx[3] = px.w - xi; dy[3] = py.w - yi; dz[3] = pz.w - zi;

        #pragma unroll
        for (int k = 0; k < 4; k++) {
            const float d2 = dx[k] * dx[k] + dy[k] * dy[k] + dz[k] * dz[k];
            const bool keep = (d2 < RC2) && (j0 + k != i);
            if (!keep) { dx[k] = 0.0f; dy[k] = 0.0f; dz[k] = 0.0f; }
        }

        // pack 12 floats into 3 float4 and stream out (48B contiguous/thread)
        float4 a = make_float4(dx[0], dy[0], dz[0], dx[1]);
        float4 b = make_float4(dy[1], dz[1], dx[2], dy[2]);
        float4 c = make_float4(dz[2], dx[3], dy[3], dz[3]);

        float4* orow = reinterpret_cast<float4*>(
            out + ((size_t)(m * N_ATM + i)) * N_ATM * 3) + threadIdx.x * 3;
        __stcs(&orow[0], a);
        __stcs(&orow[1], b);
        __stcs(&orow[2], c);
    }
}

extern "C" void kernel_launch(void* const* d_in, const int* in_sizes, int n_in,
                              void* d_out, int out_size)
{
    const float* pos = (const float*)d_in[0];
    float* out = (float*)d_out;

    dim3 grid(N_ATM / I_TILE, M_MOL);   // (64, 64)
    nbl_kernel<<<grid, NTHREADS>>>(pos, out);
}

// round 3
// speedup vs baseline: 1.1099x; 1.1099x over previous
#include <cuda_runtime.h>
#include <cstdint>

#define M_MOL 64
#define N_ATM 512
#define RC2 49.0f      // (cutoff + shell)^2 = 7^2
#define I_TILE 8       // i's per block, split across 2 thread-groups
#define NTHREADS 256

__global__ __launch_bounds__(NTHREADS) void nbl_kernel(
    const float* __restrict__ pos,   // [64, 512, 3]
    float* __restrict__ out)         // [64, 512, 512, 3]
{
    // SoA smem: conflict-free LDS.128 of 4 consecutive j
    __shared__ float sx[N_ATM], sy[N_ATM], sz[N_ATM];

    const int m = blockIdx.y;
    const float* pm = pos + (size_t)m * N_ATM * 3;

    // cooperative AoS -> SoA load (one-time, 1536 elements)
    for (int t = threadIdx.x; t < N_ATM * 3; t += NTHREADS) {
        const float v = pm[t];
        const int a = t / 3;
        const int c = t - 3 * a;
        if (c == 0)      sx[a] = v;
        else if (c == 1) sy[a] = v;
        else             sz[a] = v;
    }
    __syncthreads();

    const int ty = threadIdx.x >> 7;          // 0 or 1: which half of the i-tile
    const int tj = threadIdx.x & 127;         // j-thread within group
    const int j0 = tj * 4;
    const int i_base = blockIdx.x * I_TILE + ty * (I_TILE / 2);

    // this thread's 4 j positions, reused across 4 i's
    const float4 px = *reinterpret_cast<const float4*>(&sx[j0]);
    const float4 py = *reinterpret_cast<const float4*>(&sy[j0]);
    const float4 pz = *reinterpret_cast<const float4*>(&sz[j0]);

    #pragma unroll
    for (int ii = 0; ii < I_TILE / 2; ii++) {
        const int i = i_base + ii;
        // broadcast reads (all lanes same address)
        const float xi = sx[i];
        const float yi = sy[i];
        const float zi = sz[i];

        float dx[4], dy[4], dz[4];
        dx[0] = px.x - xi; dy[0] = py.x - yi; dz[0] = pz.x - zi;
        dx[1] = px.y - xi; dy[1] = py.y - yi; dz[1] = pz.y - zi;
        dx[2] = px.z - xi; dy[2] = py.z - yi; dz[2] = pz.z - zi;
        dx[3] = px.w - xi; dy[3] = py.w - yi; dz[3] = pz.w - zi;

        #pragma unroll
        for (int k = 0; k < 4; k++) {
            const float d2 = dx[k] * dx[k] + dy[k] * dy[k] + dz[k] * dz[k];
            const bool keep = (d2 < RC2) && (j0 + k != i);
            if (!keep) { dx[k] = 0.0f; dy[k] = 0.0f; dz[k] = 0.0f; }
        }

        // pack 12 floats into 3 float4 and stream out (48B contiguous/thread)
        float4 a = make_float4(dx[0], dy[0], dz[0], dx[1]);
        float4 b = make_float4(dy[1], dz[1], dx[2], dy[2]);
        float4 c = make_float4(dz[2], dx[3], dy[3], dz[3]);

        float4* orow = reinterpret_cast<float4*>(
            out + ((size_t)(m * N_ATM + i)) * N_ATM * 3) + tj * 3;
        __stcs(&orow[0], a);
        __stcs(&orow[1], b);
        __stcs(&orow[2], c);
    }
}

extern "C" void kernel_launch(void* const* d_in, const int* in_sizes, int n_in,
                              void* d_out, int out_size)
{
    const float* pos = (const float*)d_in[0];
    float* out = (float*)d_out;

    dim3 grid(N_ATM / I_TILE, M_MOL);   // (64, 64)
    nbl_kernel<<<grid, NTHREADS>>>(pos, out);
}